// round 1
// baseline (speedup 1.0000x reference)
#include <cuda_runtime.h>

#define B_   4
#define L_   1024
#define D_   1280
#define H_   20
#define DH_  64
#define BH_  80
#define ALPHA_ 0.48f
#define SCALE_ 0.125f   // 1/sqrt(64)

// Scratch (device globals — no allocation allowed)
__device__ float g_q[BH_ * L_ * DH_];
__device__ float g_k[BH_ * L_ * DH_];
__device__ float g_v[BH_ * L_ * DH_];
__device__ float g_ctx[B_ * L_ * D_];

// ---------------------------------------------------------------------------
// QKV projection: C = X @ W  (M=4096, N=1280, K=1280), 128x128x8 tile,
// epilogue scatters into head layout [B*H, L, DH].
// grid = (10, 32, 3); z picks Wq/Wk/Wv.
// ---------------------------------------------------------------------------
__global__ __launch_bounds__(256) void qkv_gemm(
    const float* __restrict__ X,
    const float* __restrict__ Wq,
    const float* __restrict__ Wk,
    const float* __restrict__ Wv) {
  const float* W;
  float* dst;
  if (blockIdx.z == 0)      { W = Wq; dst = g_q; }
  else if (blockIdx.z == 1) { W = Wk; dst = g_k; }
  else                      { W = Wv; dst = g_v; }

  __shared__ float As[8][128];
  __shared__ float Bs[8][128];

  const int tid = threadIdx.x;
  const int tx = tid & 15;
  const int ty = tid >> 4;
  const int row0 = blockIdx.y * 128;
  const int col0 = blockIdx.x * 128;

  // A-tile load mapping: float4 per thread per k-step
  const int ar = tid >> 1;          // 0..127
  const int ak = (tid & 1) * 4;     // 0 or 4
  // B-tile load mapping
  const int bk = tid >> 5;          // 0..7
  const int bc = (tid & 31) * 4;    // 0..124

  float acc[8][8];
#pragma unroll
  for (int i = 0; i < 8; i++)
#pragma unroll
    for (int j = 0; j < 8; j++) acc[i][j] = 0.f;

  for (int k0 = 0; k0 < D_; k0 += 8) {
    const float4 av = *(const float4*)&X[(size_t)(row0 + ar) * D_ + k0 + ak];
    const float4 bv = *(const float4*)&W[(size_t)(k0 + bk) * D_ + col0 + bc];
    As[ak + 0][ar] = av.x;
    As[ak + 1][ar] = av.y;
    As[ak + 2][ar] = av.z;
    As[ak + 3][ar] = av.w;
    *(float4*)&Bs[bk][bc] = bv;
    __syncthreads();

#pragma unroll
    for (int kk = 0; kk < 8; kk++) {
      const float4 a0 = *(const float4*)&As[kk][ty * 4];
      const float4 a1 = *(const float4*)&As[kk][64 + ty * 4];
      const float4 b0 = *(const float4*)&Bs[kk][tx * 4];
      const float4 b1 = *(const float4*)&Bs[kk][64 + tx * 4];
      const float a[8] = {a0.x, a0.y, a0.z, a0.w, a1.x, a1.y, a1.z, a1.w};
      const float b[8] = {b0.x, b0.y, b0.z, b0.w, b1.x, b1.y, b1.z, b1.w};
#pragma unroll
      for (int i = 0; i < 8; i++)
#pragma unroll
        for (int j = 0; j < 8; j++) acc[i][j] = fmaf(a[i], b[j], acc[i][j]);
    }
    __syncthreads();
  }

  // Epilogue: scatter to [B*H, L, DH]
#pragma unroll
  for (int ii = 0; ii < 2; ii++) {
#pragma unroll
    for (int i = 0; i < 4; i++) {
      const int row = row0 + ii * 64 + ty * 4 + i;
      const int b = row >> 10;
      const int l = row & 1023;
#pragma unroll
      for (int jj = 0; jj < 2; jj++) {
        const int col = col0 + jj * 64 + tx * 4;
        const int h = col >> 6;
        const int dh = col & 63;
        float4 v;
        v.x = acc[ii * 4 + i][jj * 4 + 0];
        v.y = acc[ii * 4 + i][jj * 4 + 1];
        v.z = acc[ii * 4 + i][jj * 4 + 2];
        v.w = acc[ii * 4 + i][jj * 4 + 3];
        *(float4*)&dst[((size_t)(b * H_ + h) * L_ + l) * DH_ + dh] = v;
      }
    }
  }
}

// ---------------------------------------------------------------------------
// Flash attention over kv-len 2048 (first 1024 from g_k/g_v, second 1024 from
// ALPHA * K_bg / V_bg). grid = (16, 80): x = Q tile (64 rows), y = bh.
// Writes context directly in [B, L, D] layout.
// ---------------------------------------------------------------------------
#define ATT_STRIDE 65

__global__ __launch_bounds__(256) void attn_kernel(
    const float* __restrict__ Kbg, const float* __restrict__ Vbg) {
  extern __shared__ float sm[];
  float* Qs = sm;                       // 64 x 65
  float* Ks = sm + 64 * ATT_STRIDE;     // 64 x 65
  float* Vs = sm + 2 * 64 * ATT_STRIDE; // 64 x 65
  float* Ps = sm + 3 * 64 * ATT_STRIDE; // 64 x 65

  const int tid = threadIdx.x;
  const int tx = tid & 15;
  const int ty = tid >> 4;
  const int bh = blockIdx.y;
  const int q0 = blockIdx.x * 64;

  const float* qptr = g_q + (size_t)bh * L_ * DH_;
  const float* kptr = g_k + (size_t)bh * L_ * DH_;
  const float* vptr = g_v + (size_t)bh * L_ * DH_;
  const float* kbg = Kbg + (size_t)bh * L_ * DH_;
  const float* vbg = Vbg + (size_t)bh * L_ * DH_;

  // Load Q tile, scaled by 1/sqrt(DH)
#pragma unroll
  for (int c = 0; c < 4; c++) {
    const int idx = c * 1024 + tid * 4;
    const int r = idx >> 6;
    const int cc = idx & 63;
    const float4 v = *(const float4*)&qptr[(size_t)(q0 + r) * DH_ + cc];
    Qs[r * ATT_STRIDE + cc + 0] = v.x * SCALE_;
    Qs[r * ATT_STRIDE + cc + 1] = v.y * SCALE_;
    Qs[r * ATT_STRIDE + cc + 2] = v.z * SCALE_;
    Qs[r * ATT_STRIDE + cc + 3] = v.w * SCALE_;
  }

  float m[4], l[4], O[4][4];
#pragma unroll
  for (int i = 0; i < 4; i++) {
    m[i] = -1e30f;
    l[i] = 0.f;
#pragma unroll
    for (int j = 0; j < 4; j++) O[i][j] = 0.f;
  }

  for (int t = 0; t < 32; t++) {
    __syncthreads();  // protect Ks/Vs/Ps from previous iteration's readers

    // Load K/V tile
    if (t < 16) {
      const int base = t * 64;
#pragma unroll
      for (int c = 0; c < 4; c++) {
        const int idx = c * 1024 + tid * 4;
        const int r = idx >> 6;
        const int cc = idx & 63;
        const float4 kv4 = *(const float4*)&kptr[(size_t)(base + r) * DH_ + cc];
        const float4 vv4 = *(const float4*)&vptr[(size_t)(base + r) * DH_ + cc];
        Ks[r * ATT_STRIDE + cc + 0] = kv4.x;
        Ks[r * ATT_STRIDE + cc + 1] = kv4.y;
        Ks[r * ATT_STRIDE + cc + 2] = kv4.z;
        Ks[r * ATT_STRIDE + cc + 3] = kv4.w;
        Vs[r * ATT_STRIDE + cc + 0] = vv4.x;
        Vs[r * ATT_STRIDE + cc + 1] = vv4.y;
        Vs[r * ATT_STRIDE + cc + 2] = vv4.z;
        Vs[r * ATT_STRIDE + cc + 3] = vv4.w;
      }
    } else {
      const int base = (t - 16) * 64;
#pragma unroll
      for (int c = 0; c < 4; c++) {
        const int idx = c * 1024 + tid * 4;
        const int r = idx >> 6;
        const int cc = idx & 63;
        const float4 kv4 = *(const float4*)&kbg[(size_t)(base + r) * DH_ + cc];
        const float4 vv4 = *(const float4*)&vbg[(size_t)(base + r) * DH_ + cc];
        Ks[r * ATT_STRIDE + cc + 0] = kv4.x * ALPHA_;
        Ks[r * ATT_STRIDE + cc + 1] = kv4.y * ALPHA_;
        Ks[r * ATT_STRIDE + cc + 2] = kv4.z * ALPHA_;
        Ks[r * ATT_STRIDE + cc + 3] = kv4.w * ALPHA_;
        Vs[r * ATT_STRIDE + cc + 0] = vv4.x * ALPHA_;
        Vs[r * ATT_STRIDE + cc + 1] = vv4.y * ALPHA_;
        Vs[r * ATT_STRIDE + cc + 2] = vv4.z * ALPHA_;
        Vs[r * ATT_STRIDE + cc + 3] = vv4.w * ALPHA_;
      }
    }
    __syncthreads();

    // S = Q @ K^T for this tile: thread owns rows ty*4+i, cols tx*4+j
    float s[4][4];
#pragma unroll
    for (int i = 0; i < 4; i++)
#pragma unroll
      for (int j = 0; j < 4; j++) s[i][j] = 0.f;

#pragma unroll 4
    for (int d = 0; d < 64; d++) {
      float qv[4], kv[4];
#pragma unroll
      for (int i = 0; i < 4; i++) qv[i] = Qs[(ty * 4 + i) * ATT_STRIDE + d];
#pragma unroll
      for (int j = 0; j < 4; j++) kv[j] = Ks[(tx * 4 + j) * ATT_STRIDE + d];
#pragma unroll
      for (int i = 0; i < 4; i++)
#pragma unroll
        for (int j = 0; j < 4; j++) s[i][j] = fmaf(qv[i], kv[j], s[i][j]);
    }

    // Online softmax update (row stats replicated across the 16 tx threads)
#pragma unroll
    for (int i = 0; i < 4; i++) {
      float tm = fmaxf(fmaxf(s[i][0], s[i][1]), fmaxf(s[i][2], s[i][3]));
#pragma unroll
      for (int off = 8; off >= 1; off >>= 1)
        tm = fmaxf(tm, __shfl_xor_sync(0xffffffffu, tm, off));
      const float nm = fmaxf(m[i], tm);
      const float corr = __expf(m[i] - nm);
      float tl = 0.f;
#pragma unroll
      for (int j = 0; j < 4; j++) {
        s[i][j] = __expf(s[i][j] - nm);
        tl += s[i][j];
      }
#pragma unroll
      for (int off = 8; off >= 1; off >>= 1)
        tl += __shfl_xor_sync(0xffffffffu, tl, off);
      l[i] = l[i] * corr + tl;
      m[i] = nm;
#pragma unroll
      for (int j = 0; j < 4; j++) {
        O[i][j] *= corr;
        Ps[(ty * 4 + i) * ATT_STRIDE + tx * 4 + j] = s[i][j];
      }
    }
    __syncthreads();

    // O += P @ V: thread owns rows ty*4+i, dh cols tx*4+j
#pragma unroll 4
    for (int kv = 0; kv < 64; kv++) {
      float pv[4], vv[4];
#pragma unroll
      for (int i = 0; i < 4; i++) pv[i] = Ps[(ty * 4 + i) * ATT_STRIDE + kv];
#pragma unroll
      for (int j = 0; j < 4; j++) vv[j] = Vs[kv * ATT_STRIDE + tx * 4 + j];
#pragma unroll
      for (int i = 0; i < 4; i++)
#pragma unroll
        for (int j = 0; j < 4; j++) O[i][j] = fmaf(pv[i], vv[j], O[i][j]);
    }
  }

  // Epilogue: normalize and write context in [B, L, D] layout
  const int b = bh / H_;
  const int h = bh % H_;
#pragma unroll
  for (int i = 0; i < 4; i++) {
    const int lq = q0 + ty * 4 + i;
    const float inv = 1.f / l[i];
    float4 v;
    v.x = O[i][0] * inv;
    v.y = O[i][1] * inv;
    v.z = O[i][2] * inv;
    v.w = O[i][3] * inv;
    *(float4*)&g_ctx[((size_t)b * L_ + lq) * D_ + h * DH_ + tx * 4] = v;
  }
}

// ---------------------------------------------------------------------------
// Output projection: out = ctx @ Wo + bo  (M=4096, N=1280, K=1280)
// grid = (10, 32)
// ---------------------------------------------------------------------------
__global__ __launch_bounds__(256) void out_gemm(
    const float* __restrict__ Wo, const float* __restrict__ bo,
    float* __restrict__ out) {
  __shared__ float As[8][128];
  __shared__ float Bs[8][128];

  const int tid = threadIdx.x;
  const int tx = tid & 15;
  const int ty = tid >> 4;
  const int row0 = blockIdx.y * 128;
  const int col0 = blockIdx.x * 128;

  const int ar = tid >> 1;
  const int ak = (tid & 1) * 4;
  const int bk = tid >> 5;
  const int bc = (tid & 31) * 4;

  float acc[8][8];
#pragma unroll
  for (int i = 0; i < 8; i++)
#pragma unroll
    for (int j = 0; j < 8; j++) acc[i][j] = 0.f;

  for (int k0 = 0; k0 < D_; k0 += 8) {
    const float4 av = *(const float4*)&g_ctx[(size_t)(row0 + ar) * D_ + k0 + ak];
    const float4 bv = *(const float4*)&Wo[(size_t)(k0 + bk) * D_ + col0 + bc];
    As[ak + 0][ar] = av.x;
    As[ak + 1][ar] = av.y;
    As[ak + 2][ar] = av.z;
    As[ak + 3][ar] = av.w;
    *(float4*)&Bs[bk][bc] = bv;
    __syncthreads();

#pragma unroll
    for (int kk = 0; kk < 8; kk++) {
      const float4 a0 = *(const float4*)&As[kk][ty * 4];
      const float4 a1 = *(const float4*)&As[kk][64 + ty * 4];
      const float4 b0 = *(const float4*)&Bs[kk][tx * 4];
      const float4 b1 = *(const float4*)&Bs[kk][64 + tx * 4];
      const float a[8] = {a0.x, a0.y, a0.z, a0.w, a1.x, a1.y, a1.z, a1.w};
      const float b[8] = {b0.x, b0.y, b0.z, b0.w, b1.x, b1.y, b1.z, b1.w};
#pragma unroll
      for (int i = 0; i < 8; i++)
#pragma unroll
        for (int j = 0; j < 8; j++) acc[i][j] = fmaf(a[i], b[j], acc[i][j]);
    }
    __syncthreads();
  }

#pragma unroll
  for (int ii = 0; ii < 2; ii++) {
#pragma unroll
    for (int i = 0; i < 4; i++) {
      const int row = row0 + ii * 64 + ty * 4 + i;
#pragma unroll
      for (int jj = 0; jj < 2; jj++) {
        const int col = col0 + jj * 64 + tx * 4;
        const float4 bias = *(const float4*)&bo[col];
        float4 v;
        v.x = acc[ii * 4 + i][jj * 4 + 0] + bias.x;
        v.y = acc[ii * 4 + i][jj * 4 + 1] + bias.y;
        v.z = acc[ii * 4 + i][jj * 4 + 2] + bias.z;
        v.w = acc[ii * 4 + i][jj * 4 + 3] + bias.w;
        *(float4*)&out[(size_t)row * D_ + col] = v;
      }
    }
  }
}

// ---------------------------------------------------------------------------
extern "C" void kernel_launch(void* const* d_in, const int* in_sizes, int n_in,
                              void* d_out, int out_size) {
  const float* X   = (const float*)d_in[0];
  const float* Wq  = (const float*)d_in[1];
  const float* Wk  = (const float*)d_in[2];
  const float* Wv  = (const float*)d_in[3];
  const float* Wo  = (const float*)d_in[4];
  const float* bo  = (const float*)d_in[5];
  const float* Kbg = (const float*)d_in[6];
  const float* Vbg = (const float*)d_in[7];
  float* out = (float*)d_out;

  // 1) QKV projections -> head layout scratch
  qkv_gemm<<<dim3(D_ / 128, (B_ * L_) / 128, 3), 256>>>(X, Wq, Wk, Wv);

  // 2) Flash attention with injected background KV
  const size_t smem = 4 * 64 * ATT_STRIDE * sizeof(float);  // 66560 B
  cudaFuncSetAttribute(attn_kernel, cudaFuncAttributeMaxDynamicSharedMemorySize,
                       (int)smem);
  attn_kernel<<<dim3(L_ / 64, BH_), 256, smem>>>(Kbg, Vbg);

  // 3) Output projection + bias
  out_gemm<<<dim3(D_ / 128, (B_ * L_) / 128), 256>>>(Wo, bo, out);
}

// round 3
// speedup vs baseline: 3.1369x; 3.1369x over previous
#include <cuda_runtime.h>
#include <cstdint>

#define B_   4
#define L_   1024
#define D_   1280
#define H_   20
#define DH_  64
#define BH_  80
#define ALPHA_ 0.48f
#define LOG2E_ 1.44269504088896340736f
#define QSCALE_ (0.125f * LOG2E_)   // fold 1/sqrt(dh) and log2e into Q

// ---------------------------------------------------------------------------
// Scratch (device globals — no allocation allowed)
// ---------------------------------------------------------------------------
__device__ float g_q[BH_ * L_ * DH_];
__device__ float g_k[BH_ * L_ * DH_];
__device__ float g_v[BH_ * L_ * DH_];
__device__ float g_ctx[B_ * L_ * D_];
__device__ float g_wt[4 * D_ * D_];   // transposed Wq,Wk,Wv,Wo  [N,K] row-major

// ---------------------------------------------------------------------------
// Helpers (baseline PTX only: sm_80-era features, no tcgen05/TMEM)
// ---------------------------------------------------------------------------
__device__ __forceinline__ uint32_t smem_to_u32(const void* p) {
  uint32_t a;
  asm("{ .reg .u64 t; cvta.to.shared.u64 t, %1; cvt.u32.u64 %0, t; }"
      : "=r"(a) : "l"(p));
  return a;
}

// round-to-nearest fp32 -> tf32 (returned as fp32 bit pattern, low bits zero)
__device__ __forceinline__ float f2tf_f(float x) {
  uint32_t r;
  asm("cvt.rna.tf32.f32 %0, %1;" : "=r"(r) : "f"(x));
  return __uint_as_float(r);
}

__device__ __forceinline__ float ex2(float x) {
  float r;
  asm("ex2.approx.ftz.f32 %0, %1;" : "=f"(r) : "f"(x));
  return r;
}

__device__ __forceinline__ void mma_tf32(float* c, uint32_t a0, uint32_t a1,
                                         uint32_t a2, uint32_t a3, uint32_t b0,
                                         uint32_t b1) {
  asm volatile(
      "mma.sync.aligned.m16n8k8.row.col.f32.tf32.tf32.f32 "
      "{%0,%1,%2,%3}, {%4,%5,%6,%7}, {%8,%9}, {%0,%1,%2,%3};"
      : "+f"(c[0]), "+f"(c[1]), "+f"(c[2]), "+f"(c[3])
      : "r"(a0), "r"(a1), "r"(a2), "r"(a3), "r"(b0), "r"(b1));
}

__device__ __forceinline__ void cp_async16(uint32_t saddr, const void* g) {
  asm volatile("cp.async.cg.shared.global [%0], [%1], 16;" ::"r"(saddr),
               "l"(g));
}
#define CP_COMMIT() asm volatile("cp.async.commit_group;")
#define CP_WAIT(n) asm volatile("cp.async.wait_group %0;" ::"n"(n))

// ---------------------------------------------------------------------------
// Weight transpose: g_wt[z][n][k] = W_z[k][n]
// ---------------------------------------------------------------------------
__global__ void transpose_w(const float* __restrict__ Wq,
                            const float* __restrict__ Wk,
                            const float* __restrict__ Wv,
                            const float* __restrict__ Wo) {
  __shared__ float t[32][33];
  const float* src;
  switch (blockIdx.z) {
    case 0: src = Wq; break;
    case 1: src = Wk; break;
    case 2: src = Wv; break;
    default: src = Wo; break;
  }
  float* dst = g_wt + (size_t)blockIdx.z * D_ * D_;
  const int x0 = blockIdx.x * 32;  // n
  const int y0 = blockIdx.y * 32;  // k
  const int tx = threadIdx.x;
#pragma unroll
  for (int i = threadIdx.y; i < 32; i += 8)
    t[i][tx] = src[(size_t)(y0 + i) * D_ + x0 + tx];
  __syncthreads();
#pragma unroll
  for (int i = threadIdx.y; i < 32; i += 8)
    dst[(size_t)(x0 + i) * D_ + y0 + tx] = t[tx][i];
}

// ---------------------------------------------------------------------------
// tf32 mma.sync GEMM: C[4096,1280] = A[4096,1280] @ Wt^T   (Wt is [N,K])
// Block 256 thr (8 warps, 2x4), tile 128x128, K-chunk 32, cp.async dbl-buffer.
// MODE 0: scatter to head layout [B*H, L, DH];  MODE 1: row-major + bias.
// ---------------------------------------------------------------------------
#define GM_STR 36                       // smem row stride (floats)
#define GM_BUF (128 * GM_STR)           // 4608 floats per tile buffer
#define GM_SMEM_BYTES (4 * GM_BUF * 4)  // 73728

template <int MODE>
__device__ __forceinline__ void gemm_mma_body(const float* __restrict__ A,
                                              const float* __restrict__ Wt,
                                              const float* __restrict__ bo,
                                              float* __restrict__ dst) {
  extern __shared__ float sm[];
  const uint32_t sbase = smem_to_u32(sm);
  const int tid = threadIdx.x;
  const int wid = tid >> 5, lid = tid & 31;
  const int wm = wid >> 2, wn = wid & 3;  // warp grid 2 x 4
  const int g = lid >> 2, t = lid & 3;
  const int m0 = blockIdx.y * 128, n0 = blockIdx.x * 128;

  const int ldr = tid >> 3;        // 0..31 (row group base for loads)
  const int ldc = (tid & 7) * 4;   // 0,4,..28

  float c[4][4][4];
#pragma unroll
  for (int ma = 0; ma < 4; ma++)
#pragma unroll
    for (int na = 0; na < 4; na++)
#pragma unroll
      for (int k = 0; k < 4; k++) c[ma][na][k] = 0.f;

  // prologue: prefetch chunk 0
  {
    const int k0 = 0;
#pragma unroll
    for (int i = 0; i < 4; i++) {
      const int r = i * 32 + ldr;
      cp_async16(sbase + ((0 * GM_BUF + r * GM_STR + ldc) << 2),
                 &A[(size_t)(m0 + r) * D_ + k0 + ldc]);
      cp_async16(sbase + ((2 * GM_BUF + r * GM_STR + ldc) << 2),
                 &Wt[(size_t)(n0 + r) * D_ + k0 + ldc]);
    }
    CP_COMMIT();
  }

  for (int ch = 0; ch < 40; ch++) {
    const int buf = ch & 1;
    if (ch + 1 < 40) {
      const int nbuf = (ch + 1) & 1;
      const int k0 = (ch + 1) * 32;
#pragma unroll
      for (int i = 0; i < 4; i++) {
        const int r = i * 32 + ldr;
        cp_async16(sbase + ((nbuf * GM_BUF + r * GM_STR + ldc) << 2),
                   &A[(size_t)(m0 + r) * D_ + k0 + ldc]);
        cp_async16(sbase + (((2 + nbuf) * GM_BUF + r * GM_STR + ldc) << 2),
                   &Wt[(size_t)(n0 + r) * D_ + k0 + ldc]);
      }
      CP_COMMIT();
      CP_WAIT(1);
    } else {
      CP_WAIT(0);
    }
    __syncthreads();

    const float* Ab = sm + buf * GM_BUF;
    const float* Bb = sm + (2 + buf) * GM_BUF;
#pragma unroll
    for (int ks = 0; ks < 4; ks++) {
      uint32_t af[4][4];
#pragma unroll
      for (int ma = 0; ma < 4; ma++) {
        const int row = wm * 64 + ma * 16;
        af[ma][0] = __float_as_uint(f2tf_f(Ab[(row + g) * GM_STR + ks * 8 + t]));
        af[ma][1] = __float_as_uint(f2tf_f(Ab[(row + g + 8) * GM_STR + ks * 8 + t]));
        af[ma][2] = __float_as_uint(f2tf_f(Ab[(row + g) * GM_STR + ks * 8 + t + 4]));
        af[ma][3] = __float_as_uint(f2tf_f(Ab[(row + g + 8) * GM_STR + ks * 8 + t + 4]));
      }
      uint32_t bf[4][2];
#pragma unroll
      for (int na = 0; na < 4; na++) {
        const int col = wn * 32 + na * 8 + g;
        bf[na][0] = __float_as_uint(f2tf_f(Bb[col * GM_STR + ks * 8 + t]));
        bf[na][1] = __float_as_uint(f2tf_f(Bb[col * GM_STR + ks * 8 + t + 4]));
      }
#pragma unroll
      for (int ma = 0; ma < 4; ma++)
#pragma unroll
        for (int na = 0; na < 4; na++)
          mma_tf32(c[ma][na], af[ma][0], af[ma][1], af[ma][2], af[ma][3],
                   bf[na][0], bf[na][1]);
    }
    __syncthreads();
  }

  // epilogue
#pragma unroll
  for (int ma = 0; ma < 4; ma++) {
    const int r0 = m0 + wm * 64 + ma * 16 + g;
    const int r1 = r0 + 8;
#pragma unroll
    for (int na = 0; na < 4; na++) {
      const int col = n0 + wn * 32 + na * 8 + 2 * t;
      if (MODE == 0) {
        const int h = col >> 6, dh = col & 63;
        {
          const int b = r0 >> 10, l = r0 & 1023;
          float2 v;
          v.x = c[ma][na][0];
          v.y = c[ma][na][1];
          *(float2*)&dst[((size_t)(b * H_ + h) * L_ + l) * DH_ + dh] = v;
        }
        {
          const int b = r1 >> 10, l = r1 & 1023;
          float2 v;
          v.x = c[ma][na][2];
          v.y = c[ma][na][3];
          *(float2*)&dst[((size_t)(b * H_ + h) * L_ + l) * DH_ + dh] = v;
        }
      } else {
        const float2 bias = *(const float2*)&bo[col];
        float2 v;
        v.x = c[ma][na][0] + bias.x;
        v.y = c[ma][na][1] + bias.y;
        *(float2*)&dst[(size_t)r0 * D_ + col] = v;
        v.x = c[ma][na][2] + bias.x;
        v.y = c[ma][na][3] + bias.y;
        *(float2*)&dst[(size_t)r1 * D_ + col] = v;
      }
    }
  }
}

__global__ __launch_bounds__(256) void gemm_qkv_mma(const float* __restrict__ X) {
  const int z = blockIdx.z;
  const float* Wt = g_wt + (size_t)z * D_ * D_;
  float* dst = (z == 0) ? g_q : (z == 1) ? g_k : g_v;
  gemm_mma_body<0>(X, Wt, nullptr, dst);
}

__global__ __launch_bounds__(256) void gemm_out_mma(const float* __restrict__ bo,
                                                    float* __restrict__ out) {
  gemm_mma_body<1>(g_ctx, g_wt + (size_t)3 * D_ * D_, bo, out);
}

// ---------------------------------------------------------------------------
// Flash attention with mma.sync tf32. kv-len 2048 (1024 fresh + 1024 alpha*bg)
// Block 128 thr (4 warps), Q tile 64 (16 rows/warp), KV tiles of 64.
// grid = (16, 80). Writes context in [B, L, D] layout.
// ---------------------------------------------------------------------------
#define AS 68  // smem stride (floats); 68 mod 32 = 4 -> conflict-free A/B rows

__global__ __launch_bounds__(128) void attn_mma(const float* __restrict__ Kbg,
                                                const float* __restrict__ Vbg) {
  extern __shared__ float sm[];
  float* Qs = sm;                  // 64 x 68
  float* Ks = sm + 64 * AS;        // 64 x 68
  float* Vs = sm + 2 * 64 * AS;    // 64 x 68
  float* Ps = sm + 3 * 64 * AS;    // 64 x 68

  const int tid = threadIdx.x;
  const int wid = tid >> 5, lid = tid & 31;
  const int g = lid >> 2, t = lid & 3;
  const int bh = blockIdx.y;
  const int q0 = blockIdx.x * 64;

  const float* qptr = g_q + (size_t)bh * L_ * DH_;
  const float* kptr = g_k + (size_t)bh * L_ * DH_;
  const float* vptr = g_v + (size_t)bh * L_ * DH_;
  const float* kbg = Kbg + (size_t)bh * L_ * DH_;
  const float* vbg = Vbg + (size_t)bh * L_ * DH_;

  // Load Q tile (pre-scaled to log2 domain, tf32-rounded)
#pragma unroll
  for (int i = 0; i < 8; i++) {
    const int idx = (i * 128 + tid) * 4;
    const int r = idx >> 6, cc = idx & 63;
    const float4 v = *(const float4*)&qptr[(size_t)(q0 + r) * DH_ + cc];
    float4 o;
    o.x = f2tf_f(v.x * QSCALE_);
    o.y = f2tf_f(v.y * QSCALE_);
    o.z = f2tf_f(v.z * QSCALE_);
    o.w = f2tf_f(v.w * QSCALE_);
    *(float4*)&Qs[r * AS + cc] = o;
  }

  float mrow[2] = {-1e30f, -1e30f};
  float lrow[2] = {0.f, 0.f};
  float O[8][4];
#pragma unroll
  for (int na = 0; na < 8; na++)
#pragma unroll
    for (int k = 0; k < 4; k++) O[na][k] = 0.f;

  const int pr = wid * 16;  // warp's P/Q row base

  for (int it = 0; it < 32; it++) {
    __syncthreads();  // protect Ks/Vs from previous iteration's readers

    const float* kp;
    const float* vp;
    float sc;
    if (it < 16) {
      kp = kptr + (size_t)it * 64 * DH_;
      vp = vptr + (size_t)it * 64 * DH_;
      sc = 1.f;
    } else {
      kp = kbg + (size_t)(it - 16) * 64 * DH_;
      vp = vbg + (size_t)(it - 16) * 64 * DH_;
      sc = ALPHA_;
    }
#pragma unroll
    for (int i = 0; i < 8; i++) {
      const int idx = (i * 128 + tid) * 4;
      const int r = idx >> 6, cc = idx & 63;
      const float4 kv = *(const float4*)&kp[(size_t)r * DH_ + cc];
      float4 ko;
      ko.x = f2tf_f(kv.x * sc);
      ko.y = f2tf_f(kv.y * sc);
      ko.z = f2tf_f(kv.z * sc);
      ko.w = f2tf_f(kv.w * sc);
      *(float4*)&Ks[r * AS + cc] = ko;
      const float4 vv = *(const float4*)&vp[(size_t)r * DH_ + cc];
      float4 vo;
      vo.x = f2tf_f(vv.x * sc);
      vo.y = f2tf_f(vv.y * sc);
      vo.z = f2tf_f(vv.z * sc);
      vo.w = f2tf_f(vv.w * sc);
      *(float4*)&Vs[r * AS + cc] = vo;
    }
    __syncthreads();

    // S = Q @ K^T : warp computes rows [pr, pr+16), cols [0,64)
    float s[8][4];
#pragma unroll
    for (int na = 0; na < 8; na++)
#pragma unroll
      for (int k = 0; k < 4; k++) s[na][k] = 0.f;

#pragma unroll
    for (int ks = 0; ks < 8; ks++) {
      const uint32_t a0 = __float_as_uint(Qs[(pr + g) * AS + ks * 8 + t]);
      const uint32_t a1 = __float_as_uint(Qs[(pr + g + 8) * AS + ks * 8 + t]);
      const uint32_t a2 = __float_as_uint(Qs[(pr + g) * AS + ks * 8 + t + 4]);
      const uint32_t a3 = __float_as_uint(Qs[(pr + g + 8) * AS + ks * 8 + t + 4]);
#pragma unroll
      for (int na = 0; na < 8; na++) {
        const uint32_t b0 = __float_as_uint(Ks[(na * 8 + g) * AS + ks * 8 + t]);
        const uint32_t b1 = __float_as_uint(Ks[(na * 8 + g) * AS + ks * 8 + t + 4]);
        mma_tf32(s[na], a0, a1, a2, a3, b0, b1);
      }
    }

    // Online softmax (log2 domain). Thread owns rows pr+g and pr+g+8.
    float mx0 = -1e30f, mx1 = -1e30f;
#pragma unroll
    for (int na = 0; na < 8; na++) {
      mx0 = fmaxf(mx0, fmaxf(s[na][0], s[na][1]));
      mx1 = fmaxf(mx1, fmaxf(s[na][2], s[na][3]));
    }
    mx0 = fmaxf(mx0, __shfl_xor_sync(0xffffffffu, mx0, 1));
    mx0 = fmaxf(mx0, __shfl_xor_sync(0xffffffffu, mx0, 2));
    mx1 = fmaxf(mx1, __shfl_xor_sync(0xffffffffu, mx1, 1));
    mx1 = fmaxf(mx1, __shfl_xor_sync(0xffffffffu, mx1, 2));

    const float nm0 = fmaxf(mrow[0], mx0);
    const float nm1 = fmaxf(mrow[1], mx1);
    const float corr0 = ex2(mrow[0] - nm0);
    const float corr1 = ex2(mrow[1] - nm1);

    float sum0 = 0.f, sum1 = 0.f;
#pragma unroll
    for (int na = 0; na < 8; na++) {
      s[na][0] = ex2(s[na][0] - nm0);
      s[na][1] = ex2(s[na][1] - nm0);
      s[na][2] = ex2(s[na][2] - nm1);
      s[na][3] = ex2(s[na][3] - nm1);
      sum0 += s[na][0] + s[na][1];
      sum1 += s[na][2] + s[na][3];
    }
    sum0 += __shfl_xor_sync(0xffffffffu, sum0, 1);
    sum0 += __shfl_xor_sync(0xffffffffu, sum0, 2);
    sum1 += __shfl_xor_sync(0xffffffffu, sum1, 1);
    sum1 += __shfl_xor_sync(0xffffffffu, sum1, 2);

    lrow[0] = lrow[0] * corr0 + sum0;
    lrow[1] = lrow[1] * corr1 + sum1;
    mrow[0] = nm0;
    mrow[1] = nm1;

#pragma unroll
    for (int na = 0; na < 8; na++) {
      O[na][0] *= corr0;
      O[na][1] *= corr0;
      O[na][2] *= corr1;
      O[na][3] *= corr1;
      // store P (tf32-rounded) into warp-private Ps rows
      Ps[(pr + g) * AS + na * 8 + 2 * t] = f2tf_f(s[na][0]);
      Ps[(pr + g) * AS + na * 8 + 2 * t + 1] = f2tf_f(s[na][1]);
      Ps[(pr + g + 8) * AS + na * 8 + 2 * t] = f2tf_f(s[na][2]);
      Ps[(pr + g + 8) * AS + na * 8 + 2 * t + 1] = f2tf_f(s[na][3]);
    }
    __syncwarp();

    // O += P @ V
#pragma unroll
    for (int ks = 0; ks < 8; ks++) {
      const uint32_t a0 = __float_as_uint(Ps[(pr + g) * AS + ks * 8 + t]);
      const uint32_t a1 = __float_as_uint(Ps[(pr + g + 8) * AS + ks * 8 + t]);
      const uint32_t a2 = __float_as_uint(Ps[(pr + g) * AS + ks * 8 + t + 4]);
      const uint32_t a3 = __float_as_uint(Ps[(pr + g + 8) * AS + ks * 8 + t + 4]);
#pragma unroll
      for (int na = 0; na < 8; na++) {
        const uint32_t b0 = __float_as_uint(Vs[(ks * 8 + t) * AS + na * 8 + g]);
        const uint32_t b1 = __float_as_uint(Vs[(ks * 8 + t + 4) * AS + na * 8 + g]);
        mma_tf32(O[na], a0, a1, a2, a3, b0, b1);
      }
    }
    __syncwarp();
  }

  // Epilogue: normalize and write [B, L, D]
  const int b = bh / H_;
  const int h = bh % H_;
  const float inv0 = 1.f / lrow[0];
  const float inv1 = 1.f / lrow[1];
  const int r0 = q0 + pr + g;
  const int r1 = r0 + 8;
#pragma unroll
  for (int na = 0; na < 8; na++) {
    const int dh = na * 8 + 2 * t;
    float2 v;
    v.x = O[na][0] * inv0;
    v.y = O[na][1] * inv0;
    *(float2*)&g_ctx[((size_t)b * L_ + r0) * D_ + h * DH_ + dh] = v;
    v.x = O[na][2] * inv1;
    v.y = O[na][3] * inv1;
    *(float2*)&g_ctx[((size_t)b * L_ + r1) * D_ + h * DH_ + dh] = v;
  }
}

// ---------------------------------------------------------------------------
extern "C" void kernel_launch(void* const* d_in, const int* in_sizes, int n_in,
                              void* d_out, int out_size) {
  const float* X   = (const float*)d_in[0];
  const float* Wq  = (const float*)d_in[1];
  const float* Wk  = (const float*)d_in[2];
  const float* Wv  = (const float*)d_in[3];
  const float* Wo  = (const float*)d_in[4];
  const float* bo  = (const float*)d_in[5];
  const float* Kbg = (const float*)d_in[6];
  const float* Vbg = (const float*)d_in[7];
  float* out = (float*)d_out;

  // 0) Transpose weights into [N,K]
  transpose_w<<<dim3(D_ / 32, D_ / 32, 4), dim3(32, 8)>>>(Wq, Wk, Wv, Wo);

  // 1) QKV projections (mma.sync tf32)
  cudaFuncSetAttribute(gemm_qkv_mma, cudaFuncAttributeMaxDynamicSharedMemorySize,
                       GM_SMEM_BYTES);
  gemm_qkv_mma<<<dim3(10, 32, 3), 256, GM_SMEM_BYTES>>>(X);

  // 2) Flash attention (mma.sync tf32)
  const int att_smem = 4 * 64 * AS * sizeof(float);  // 69632
  cudaFuncSetAttribute(attn_mma, cudaFuncAttributeMaxDynamicSharedMemorySize,
                       att_smem);
  attn_mma<<<dim3(L_ / 64, BH_), 128, att_smem>>>(Kbg, Vbg);

  // 3) Output projection + bias (mma.sync tf32)
  cudaFuncSetAttribute(gemm_out_mma, cudaFuncAttributeMaxDynamicSharedMemorySize,
                       GM_SMEM_BYTES);
  gemm_out_mma<<<dim3(10, 32), 256, GM_SMEM_BYTES>>>(bo, out);
}